// round 6
// baseline (speedup 1.0000x reference)
#include <cuda_runtime.h>

typedef unsigned long long u64;

#define B_  64
#define IC  512
#define ID  128
#define NC  32
#define DC  32
#define IT  4            // i-tiles
#define TI  128          // IC / IT

#define XST 132          // stride for xs and xsT rows (16B-aligned, conflict-free)
#define CST 36           // stride for cs / wvT rows

#define OFF_XS  0
#define OFF_XT  (TI * XST)                   // 16896
#define OFF_C   (OFF_XT + ID * XST)          // 33792
#define OFF_WT  (OFF_C + TI * CST)           // 38400
#define SMEM_FLOATS (OFF_WT + ID * CST)      // 43008
#define SMEM_BYTES  (SMEM_FLOATS * 4)        // 172032

// ---- device scratch ----
__device__ float g_P [B_ * NC * IC];         // routing logits (4 MB)
__device__ float g_WV[B_ * NC * ID];         // wv = W @ v     (1 MB)
__device__ float g_Yp[IT * B_ * NC * ID];    // partial Y      (4 MB)

// ---- f32x2 helpers ----
__device__ __forceinline__ u64 pack2(float x) {
    u64 r; unsigned u = __float_as_uint(x);
    asm("mov.b64 %0, {%1, %1};" : "=l"(r) : "r"(u));
    return r;
}
__device__ __forceinline__ void unpack2(u64 v, float& a, float& b) {
    unsigned lo, hi;
    asm("mov.b64 {%0, %1}, %2;" : "=r"(lo), "=r"(hi) : "l"(v));
    a = __uint_as_float(lo); b = __uint_as_float(hi);
}
__device__ __forceinline__ u64 ffma2(u64 a, u64 b, u64 c) {
    u64 d;
    asm("fma.rn.f32x2 %0, %1, %2, %3;" : "=l"(d) : "l"(a), "l"(b), "l"(c));
    return d;
}

// ============================================================
// Fused per-iteration kernel. grid (IT, B_), block 256, 172KB smem.
// iter 0:  c = softmax(b0 tile)                    -> partial Y
// iter 1:  uv = X@wv; b1 = b0+uv (store g_P); softmax -> partial Y
// iter 2:  uv = X@wv; b2 = g_P+uv (no store); softmax -> partial Y
// ============================================================
__global__ __launch_bounds__(256) void k_fused(
    const float* __restrict__ X,
    const float* __restrict__ B0,
    int iter)
{
    extern __shared__ float sm[];
    float* xs  = sm + OFF_XS;   // [TI][XST]  i-major
    float* xsT = sm + OFF_XT;   // [ID][XST]  d-major
    float* cs  = sm + OFF_C;    // [TI][CST]  i-major logits/coeffs
    float* wvT = sm + OFF_WT;   // [ID][CST]  wv transposed [d][n]

    const int b    = blockIdx.y;
    const int tt   = blockIdx.x;
    const int i0   = tt * TI;
    const int t    = threadIdx.x;
    const int lane = t & 31;
    const int w    = t >> 5;
    const int n0   = w * 4;     // warp owns capsules n0..n0+3

    // ---- stage xs (coalesced) ----
    {
        const float4* Xb = (const float4*)(X + ((size_t)b * IC + i0) * ID);
        for (int u = t; u < TI * 32; u += 256) {
            const int r = u >> 5, q = u & 31;
            *(float4*)(xs + r * XST + q * 4) = Xb[r * 32 + q];
        }
    }

    if (iter == 0) {
        // logits from b0: n-major gmem -> i-major cs
        const float* Pb = B0 + (size_t)b * NC * IC + i0;
        for (int u = t; u < NC * 32; u += 256) {
            const int n = u >> 5, q = u & 31;
            const float4 p4 = *(const float4*)(Pb + (size_t)n * IC + 4 * q);
            cs[(4 * q + 0) * CST + n] = p4.x;
            cs[(4 * q + 1) * CST + n] = p4.y;
            cs[(4 * q + 2) * CST + n] = p4.z;
            cs[(4 * q + 3) * CST + n] = p4.w;
        }
        __syncthreads();
    } else {
        // stage wv transposed: g_WV[b][n][d] -> wvT[d][n]
        {
            const float* WVb = g_WV + (size_t)b * NC * ID;
            for (int u = t; u < NC * 32; u += 256) {
                const int n = u >> 5, q = u & 31;
                const float4 v4 = *(const float4*)(WVb + n * ID + 4 * q);
                wvT[(4 * q + 0) * CST + n] = v4.x;
                wvT[(4 * q + 1) * CST + n] = v4.y;
                wvT[(4 * q + 2) * CST + n] = v4.z;
                wvT[(4 * q + 3) * CST + n] = v4.w;
            }
        }
        __syncthreads();

        // in-smem transpose xs -> xsT (reads 4-way conflicted, writes clean)
        for (int u = t; u < TI * ID; u += 256) {
            const int d = u >> 7, i = u & 127;
            xsT[d * XST + i] = xs[i * XST + d];
        }
        __syncthreads();

        // ---- phase 1: uv[n][i] = sum_d x[i][d] * wv[n][d]  (f32x2, n-pairs)
        // thread tile: 4 n (2 pairs) x 4 i (i = 4*lane + j)
        u64 acc[2][4];
#pragma unroll
        for (int p = 0; p < 2; p++)
#pragma unroll
            for (int j = 0; j < 4; j++) acc[p][j] = 0ull;

#pragma unroll 4
        for (int d = 0; d < ID; d++) {
            const ulonglong2 wv2 = *(const ulonglong2*)(wvT + d * CST + n0); // (n0,n0+1),(n0+2,n0+3)
            const float4 xv = *(const float4*)(xsT + d * XST + 4 * lane);
            const u64 bx0 = pack2(xv.x), bx1 = pack2(xv.y);
            const u64 bx2 = pack2(xv.z), bx3 = pack2(xv.w);
            acc[0][0] = ffma2(wv2.x, bx0, acc[0][0]);
            acc[0][1] = ffma2(wv2.x, bx1, acc[0][1]);
            acc[0][2] = ffma2(wv2.x, bx2, acc[0][2]);
            acc[0][3] = ffma2(wv2.x, bx3, acc[0][3]);
            acc[1][0] = ffma2(wv2.y, bx0, acc[1][0]);
            acc[1][1] = ffma2(wv2.y, bx1, acc[1][1]);
            acc[1][2] = ffma2(wv2.y, bx2, acc[1][2]);
            acc[1][3] = ffma2(wv2.y, bx3, acc[1][3]);
        }

        // epilogue: b_new = b_prev + uv -> cs (and g_P on iter 1)
        float a[4][4];
#pragma unroll
        for (int j = 0; j < 4; j++) {
            unpack2(acc[0][j], a[0][j], a[1][j]);
            unpack2(acc[1][j], a[2][j], a[3][j]);
        }
        const float* Pprev = (iter == 1) ? B0 : g_P;
#pragma unroll
        for (int k = 0; k < 4; k++) {
            const size_t off = ((size_t)b * NC + n0 + k) * IC + i0 + 4 * lane;
            float4 p4 = *(const float4*)(Pprev + off);
            p4.x += a[k][0]; p4.y += a[k][1]; p4.z += a[k][2]; p4.w += a[k][3];
            if (iter == 1) *(float4*)(g_P + off) = p4;
            cs[(4 * lane + 0) * CST + n0 + k] = p4.x;
            cs[(4 * lane + 1) * CST + n0 + k] = p4.y;
            cs[(4 * lane + 2) * CST + n0 + k] = p4.z;
            cs[(4 * lane + 3) * CST + n0 + k] = p4.w;
        }
        __syncthreads();
    }

    // ---- softmax over n: 2 threads per i-row ----
    {
        const int i = t >> 1;
        const int h = (t & 1) << 4;
        float* row = cs + i * CST + h;
        float m = row[0];
#pragma unroll
        for (int n = 1; n < 16; n++) m = fmaxf(m, row[n]);
        m = fmaxf(m, __shfl_xor_sync(0xffffffffu, m, 1));
        float s = 0.f;
#pragma unroll
        for (int n = 0; n < 16; n++) {
            const float e = __expf(row[n] - m);
            row[n] = e;
            s += e;
        }
        s += __shfl_xor_sync(0xffffffffu, s, 1);
        const float r = __fdividef(1.f, s);
#pragma unroll
        for (int n = 0; n < 16; n++) row[n] *= r;
    }
    __syncthreads();

    // ---- phase 3: Y[n][d] = sum_i c[i][n] * x[i][d]  (f32x2, d-pairs)
    // thread tile: 4 n x 4 d (d = 4*lane + j); x pairs natural from LDS.128
    {
        u64 y[4][2];
#pragma unroll
        for (int k = 0; k < 4; k++) { y[k][0] = 0ull; y[k][1] = 0ull; }

#pragma unroll 4
        for (int i = 0; i < TI; i++) {
            const float4 c4 = *(const float4*)(cs + i * CST + n0);   // warp-broadcast
            const ulonglong2 x2 = *(const ulonglong2*)(xs + i * XST + 4 * lane);
            const u64 bc0 = pack2(c4.x), bc1 = pack2(c4.y);
            const u64 bc2 = pack2(c4.z), bc3 = pack2(c4.w);
            y[0][0] = ffma2(bc0, x2.x, y[0][0]);
            y[0][1] = ffma2(bc0, x2.y, y[0][1]);
            y[1][0] = ffma2(bc1, x2.x, y[1][0]);
            y[1][1] = ffma2(bc1, x2.y, y[1][1]);
            y[2][0] = ffma2(bc2, x2.x, y[2][0]);
            y[2][1] = ffma2(bc2, x2.y, y[2][1]);
            y[3][0] = ffma2(bc3, x2.x, y[3][0]);
            y[3][1] = ffma2(bc3, x2.y, y[3][1]);
        }

#pragma unroll
        for (int k = 0; k < 4; k++) {
            ulonglong2 o; o.x = y[k][0]; o.y = y[k][1];
            *(ulonglong2*)(g_Yp + (((size_t)tt * B_ + b) * NC + n0 + k) * ID + 4 * lane) = o;
        }
    }
}

// ============================================================
// Reduce partial Y; s = Y@W; v = squash(s); wv = W@v or OUT.
// grid (B_/4, NC) = (16,32), block 256: 4 batches per block.
// ============================================================
__global__ __launch_bounds__(256) void k_svwv(
    const float* __restrict__ W,
    float* __restrict__ OUT,
    int final_iter)
{
    __shared__ float WT[DC * XST];   // WT[c][d], stride 132
    __shared__ float Ysm[4][ID];
    __shared__ float vsm[4][NC];

    const int n  = blockIdx.y;
    const int b0 = blockIdx.x * 4;
    const int t  = threadIdx.x;
    const int lane = t & 31;
    const int w  = t >> 5;

    // stage W[n] transposed: W[n][d][c] -> WT[c][d]
    {
        const float* Wn = W + (size_t)n * ID * DC;
        for (int u = t; u < ID * DC; u += 256) {
            const int d = u >> 5, c = u & 31;
            WT[c * XST + d] = Wn[u];
        }
    }
    // reduce IT partial Y tiles
    for (int u = t; u < 4 * ID; u += 256) {
        const int bb = u >> 7, d = u & 127;
        float acc = 0.f;
#pragma unroll
        for (int p = 0; p < IT; p++)
            acc += g_Yp[(((size_t)p * B_ + b0 + bb) * NC + n) * ID + d];
        Ysm[bb][d] = acc;
    }
    __syncthreads();

    // s-dot + squash: warps 0-3, one batch each, lane = output c
    if (w < 4) {
        const int bb = w, c = lane;
        float s = 0.f;
#pragma unroll 8
        for (int k = 0; k < ID / 4; k++) {
            const float4 wq = *(const float4*)(WT + c * XST + 4 * k);
            const float4 yq = *(const float4*)(&Ysm[bb][4 * k]);
            s = fmaf(wq.x, yq.x, s);
            s = fmaf(wq.y, yq.y, s);
            s = fmaf(wq.z, yq.z, s);
            s = fmaf(wq.w, yq.w, s);
        }
        float sn = s * s;
#pragma unroll
        for (int o = 16; o; o >>= 1) sn += __shfl_xor_sync(0xffffffffu, sn, o);
        const float v = s * sn / ((1.f + sn) * (sqrtf(sn) + 1e-8f));

        if (final_iter)
            OUT[(((size_t)(b0 + bb)) * NC + n) * DC + c] = v;
        else
            vsm[bb][c] = v;
    }
    if (final_iter) return;
    __syncthreads();

    // wv[d] = sum_c W[n][d][c] * v[c] ; all 8 warps, 2 d per thread
    for (int u = t; u < 4 * ID; u += 256) {
        const int bb = u >> 7, d = u & 127;
        float acc = 0.f;
#pragma unroll
        for (int c = 0; c < NC; c++)
            acc = fmaf(WT[c * XST + d], vsm[bb][c], acc);
        g_WV[(((size_t)(b0 + bb)) * NC + n) * ID + d] = acc;
    }
}

// ============================================================
// launch
// ============================================================
extern "C" void kernel_launch(void* const* d_in, const int* in_sizes, int n_in,
                              void* d_out, int out_size) {
    const float *X = nullptr, *W = nullptr, *B0 = nullptr;
    for (int i = 0; i < n_in; i++) {
        if      (in_sizes[i] == B_ * IC * ID) X  = (const float*)d_in[i];
        else if (in_sizes[i] == NC * ID * DC) W  = (const float*)d_in[i];
        else if (in_sizes[i] == B_ * NC * IC) B0 = (const float*)d_in[i];
    }
    float* OUT = (float*)d_out;

    cudaFuncSetAttribute(k_fused,
                         cudaFuncAttributeMaxDynamicSharedMemorySize, SMEM_BYTES);

    k_fused<<<dim3(IT, B_), 256, SMEM_BYTES>>>(X, B0, 0);
    k_svwv <<<dim3(B_ / 4, NC), 256>>>(W, OUT, 0);
    k_fused<<<dim3(IT, B_), 256, SMEM_BYTES>>>(X, B0, 1);
    k_svwv <<<dim3(B_ / 4, NC), 256>>>(W, OUT, 0);
    k_fused<<<dim3(IT, B_), 256, SMEM_BYTES>>>(X, B0, 2);
    k_svwv <<<dim3(B_ / 4, NC), 256>>>(W, OUT, 1);
}

// round 7
// speedup vs baseline: 1.0852x; 1.0852x over previous
#include <cuda_runtime.h>

typedef unsigned long long u64;

#define B_  64
#define IC  512
#define ID  128
#define NC  32
#define DC  32
#define IT  4            // i-tiles
#define TI  128          // IC / IT

#define XS_STRIDE 132    // padded row for X tile (16B-aligned, conflict-free both axes)
#define C_STRIDE  36     // padded row for c/logits (16B-aligned for LDS.128)

#define OFF_XS 0
#define OFF_C  (TI * XS_STRIDE)                 // 16896
#define OFF_WV (OFF_C + TI * C_STRIDE)          // 21504
#define SMEM_FLOATS (OFF_WV + NC * ID)          // 25600
#define SMEM_BYTES  (SMEM_FLOATS * 4)           // 102400

// ---- device scratch (static; no allocations) ----
__device__ float g_P [B_ * NC * IC];            // routing logits (4 MB)
__device__ float g_WV[B_ * NC * ID];            // wv = W @ v     (1 MB)
__device__ float g_Yp[IT * B_ * NC * ID];       // partial Y      (4 MB)

// ---- f32x2 helpers (reduction-dim pairing: no packs needed) ----
__device__ __forceinline__ u64 ffma2(u64 a, u64 b, u64 c) {
    u64 d;
    asm("fma.rn.f32x2 %0, %1, %2, %3;" : "=l"(d) : "l"(a), "l"(b), "l"(c));
    return d;
}
__device__ __forceinline__ float pairsum(u64 v) {
    unsigned lo, hi;
    asm("mov.b64 {%0, %1}, %2;" : "=r"(lo), "=r"(hi) : "l"(v));
    return __uint_as_float(lo) + __uint_as_float(hi);
}

// ============================================================
// Fused per-iteration kernel. grid (IT, B_), block 256, 100KB smem.
// iter 0: c = softmax(b0 tile)                  -> partial Y
// iter 1: uv = X@wv; b1 = b0+uv (write g_P); softmax -> partial Y
// iter 2: uv = X@wv; b2 = g_P+uv (no write);  softmax -> partial Y
// ============================================================
__global__ __launch_bounds__(256) void k_fused(
    const float* __restrict__ X,
    const float* __restrict__ B0,
    int iter)
{
    extern __shared__ float sm[];
    float* xs  = sm + OFF_XS;   // [TI][XS_STRIDE]
    float* cs  = sm + OFF_C;    // [TI][C_STRIDE]
    float* wvs = sm + OFF_WV;   // [NC][ID]

    const int b    = blockIdx.y;
    const int tt   = blockIdx.x;
    const int i0   = tt * TI;
    const int t    = threadIdx.x;
    const int lane = t & 31;
    const int w    = t >> 5;
    const int n0   = w * 4;     // each warp owns 4 capsule outputs

    // ---- stage X tile: X[b][i0+r][:] -> xs[r][:] (coalesced) ----
    {
        const float4* Xb = (const float4*)(X + ((size_t)b * IC + i0) * ID);
        for (int u = t; u < TI * 32; u += 256) {
            const int r = u >> 5, q = u & 31;
            *(float4*)(xs + r * XS_STRIDE + q * 4) = Xb[r * 32 + q];
        }
    }

    if (iter == 0) {
        // logits tile straight from b0
        const float* Pb = B0 + (size_t)b * NC * IC + i0;
        for (int u = t; u < NC * TI; u += 256) {
            const int n = u >> 7, i = u & 127;
            cs[i * C_STRIDE + n] = Pb[(size_t)n * IC + i];
        }
        __syncthreads();
    } else {
        // stage wv[b]
        for (int u = t; u < NC * ID; u += 256)
            wvs[u] = g_WV[(size_t)b * NC * ID + u];
        __syncthreads();

        // ---- phase 1: uv[n][i] = sum_d xs[i][d] * wv[n][d] ----
        // f32x2 pairing along the REDUCTION dim d: both operands are
        // d-contiguous, so the existing LDS.128s are reinterpreted as
        // two f32x2 pairs each. acc holds paired partial sums.
        // thread tile: 4 n (n0..n0+3) x 4 i (lane + 32*jj)
        u64 acc[4][4];
#pragma unroll
        for (int k = 0; k < 4; k++)
#pragma unroll
            for (int jj = 0; jj < 4; jj++) acc[k][jj] = 0ull;

#pragma unroll 2
        for (int d = 0; d < ID; d += 4) {
            ulonglong2 xq[4];
#pragma unroll
            for (int jj = 0; jj < 4; jj++)
                xq[jj] = *(const ulonglong2*)(xs + (lane + 32 * jj) * XS_STRIDE + d);
#pragma unroll
            for (int k = 0; k < 4; k++) {
                const ulonglong2 wq = *(const ulonglong2*)(wvs + (n0 + k) * ID + d);
#pragma unroll
                for (int jj = 0; jj < 4; jj++) {
                    acc[k][jj] = ffma2(wq.x, xq[jj].x, acc[k][jj]);
                    acc[k][jj] = ffma2(wq.y, xq[jj].y, acc[k][jj]);
                }
            }
        }

        // new logits = prev + (lo+hi of pair); write-through on iter 1
        const float* Pprev = (iter == 1) ? B0 : g_P;
#pragma unroll
        for (int k = 0; k < 4; k++)
#pragma unroll
            for (int jj = 0; jj < 4; jj++) {
                const size_t off = ((size_t)b * NC + n0 + k) * IC + i0 + lane + 32 * jj;
                const float nb = Pprev[off] + pairsum(acc[k][jj]);
                if (iter == 1) g_P[off] = nb;
                cs[(lane + 32 * jj) * C_STRIDE + n0 + k] = nb;
            }
        __syncthreads();
    }

    // ---- softmax over n, 2 threads per i-row (halves n-range each) ----
    {
        const int i = t >> 1;
        const int h = (t & 1) << 4;
        float* row = cs + i * C_STRIDE + h;
        float m = row[0];
#pragma unroll
        for (int n = 1; n < 16; n++) m = fmaxf(m, row[n]);
        m = fmaxf(m, __shfl_xor_sync(0xffffffffu, m, 1));
        float s = 0.f;
#pragma unroll
        for (int n = 0; n < 16; n++) {
            const float e = __expf(row[n] - m);
            row[n] = e;
            s += e;
        }
        s += __shfl_xor_sync(0xffffffffu, s, 1);
        const float r = __fdividef(1.f, s);
#pragma unroll
        for (int n = 0; n < 16; n++) row[n] *= r;
    }
    __syncthreads();

    // ---- phase 3: partial Y[n][d] = sum_i c[i][n] * xs[i][d] ----
    // per thread: 4 n (n0..n0+3, broadcast LDS.128) x 4 d (lane*4)
    {
        const int d0 = lane * 4;
        float y[4][4];
#pragma unroll
        for (int k = 0; k < 4; k++)
#pragma unroll
            for (int j = 0; j < 4; j++) y[k][j] = 0.f;

#pragma unroll 2
        for (int i = 0; i < TI; i++) {
            const float4 cq = *(const float4*)(cs + i * C_STRIDE + n0);
            const float4 xv = *(const float4*)(xs + i * XS_STRIDE + d0);
            y[0][0] = fmaf(cq.x, xv.x, y[0][0]);
            y[0][1] = fmaf(cq.x, xv.y, y[0][1]);
            y[0][2] = fmaf(cq.x, xv.z, y[0][2]);
            y[0][3] = fmaf(cq.x, xv.w, y[0][3]);
            y[1][0] = fmaf(cq.y, xv.x, y[1][0]);
            y[1][1] = fmaf(cq.y, xv.y, y[1][1]);
            y[1][2] = fmaf(cq.y, xv.z, y[1][2]);
            y[1][3] = fmaf(cq.y, xv.w, y[1][3]);
            y[2][0] = fmaf(cq.z, xv.x, y[2][0]);
            y[2][1] = fmaf(cq.z, xv.y, y[2][1]);
            y[2][2] = fmaf(cq.z, xv.z, y[2][2]);
            y[2][3] = fmaf(cq.z, xv.w, y[2][3]);
            y[3][0] = fmaf(cq.w, xv.x, y[3][0]);
            y[3][1] = fmaf(cq.w, xv.y, y[3][1]);
            y[3][2] = fmaf(cq.w, xv.z, y[3][2]);
            y[3][3] = fmaf(cq.w, xv.w, y[3][3]);
        }

        float* Yp = g_Yp + (((size_t)tt * B_ + b) * NC + n0) * ID + d0;
#pragma unroll
        for (int k = 0; k < 4; k++)
            *(float4*)(Yp + (size_t)k * ID) = make_float4(y[k][0], y[k][1], y[k][2], y[k][3]);
    }
}

// ============================================================
// svwv: one (n, b) pair per 64-thread block, grid (NC, B_) = 2048.
// Reduce partial Y; s = Y@W[n]; v = squash(s); wv = W[n]@v or OUT.
// W[n] staged pad-33: conflict-free for BOTH c-lane dots (s) and
// d-lane dots (wv).
// ============================================================
__global__ __launch_bounds__(64) void k_svwv(
    const float* __restrict__ W,
    float* __restrict__ OUT,
    int final_iter)
{
    __shared__ float Wsm[ID * 33];   // Wsm[d*33 + c]
    __shared__ float Ysm[ID];
    __shared__ float vsm[DC];

    const int n = blockIdx.x;
    const int b = blockIdx.y;
    const int t = threadIdx.x;
    const int lane = t & 31;

    // stage W[n] (coalesced LDG, conflict-free STS)
    {
        const float* Wn = W + (size_t)n * ID * DC;
        for (int u = t; u < ID * DC; u += 64) {
            const int d = u >> 5, c = u & 31;
            Wsm[d * 33 + c] = Wn[u];
        }
    }
    // reduce IT partial Y tiles (float4, threads 0..31)
    if (t < 32) {
        float4 acc = make_float4(0.f, 0.f, 0.f, 0.f);
#pragma unroll
        for (int p = 0; p < IT; p++) {
            const float4 y4 = ((const float4*)(g_Yp + (((size_t)p * B_ + b) * NC + n) * ID))[t];
            acc.x += y4.x; acc.y += y4.y; acc.z += y4.z; acc.w += y4.w;
        }
        ((float4*)Ysm)[t] = acc;
    }
    __syncthreads();

    // warp 0: s-dot (lane = c), squash
    if (t < 32) {
        const int c = lane;
        float s = 0.f;
#pragma unroll 8
        for (int d = 0; d < ID; d++)
            s = fmaf(Ysm[d], Wsm[d * 33 + c], s);

        float sn = s * s;
#pragma unroll
        for (int o = 16; o; o >>= 1) sn += __shfl_xor_sync(0xffffffffu, sn, o);
        const float v = s * sn / ((1.f + sn) * (sqrtf(sn) + 1e-8f));

        if (final_iter)
            OUT[(((size_t)b) * NC + n) * DC + c] = v;
        else
            vsm[c] = v;
    }
    if (final_iter) return;
    __syncthreads();

    // wv[d] = sum_c W[n][d][c] * v[c] ; 64 threads x 2 d each
    float* wvout = g_WV + (((size_t)b) * NC + n) * ID;
#pragma unroll
    for (int r = 0; r < 2; r++) {
        const int d = t + 64 * r;
        float acc = 0.f;
#pragma unroll
        for (int c = 0; c < DC; c++)
            acc = fmaf(Wsm[d * 33 + c], vsm[c], acc);
        wvout[d] = acc;
    }
}

// ============================================================
// launch
// ============================================================
extern "C" void kernel_launch(void* const* d_in, const int* in_sizes, int n_in,
                              void* d_out, int out_size) {
    const float *X = nullptr, *W = nullptr, *B0 = nullptr;
    for (int i = 0; i < n_in; i++) {
        if      (in_sizes[i] == B_ * IC * ID) X  = (const float*)d_in[i];
        else if (in_sizes[i] == NC * ID * DC) W  = (const float*)d_in[i];
        else if (in_sizes[i] == B_ * NC * IC) B0 = (const float*)d_in[i];
    }
    float* OUT = (float*)d_out;

    cudaFuncSetAttribute(k_fused,
                         cudaFuncAttributeMaxDynamicSharedMemorySize, SMEM_BYTES);

    k_fused<<<dim3(IT, B_), 256, SMEM_BYTES>>>(X, B0, 0);
    k_svwv <<<dim3(NC, B_), 64>>>(W, OUT, 0);
    k_fused<<<dim3(IT, B_), 256, SMEM_BYTES>>>(X, B0, 1);
    k_svwv <<<dim3(NC, B_), 64>>>(W, OUT, 0);
    k_fused<<<dim3(IT, B_), 256, SMEM_BYTES>>>(X, B0, 2);
    k_svwv <<<dim3(NC, B_), 64>>>(W, OUT, 1);
}

// round 9
// speedup vs baseline: 1.3650x; 1.2578x over previous
#include <cuda_runtime.h>

#define B_  64
#define IC  512
#define ID  128
#define NC  32
#define DC  32
#define IT  4            // i-tiles
#define TI  128          // IC / IT
#define NBLK (IT * B_)   // 256 blocks — single wave at 2 CTA/SM (296 slots)

#define XS_STRIDE 132
#define C_STRIDE  36

#define OFF_XS 0
#define OFF_C  (TI * XS_STRIDE)                 // 16896 floats
#define OFF_WV (OFF_C + TI * C_STRIDE)          // 21504
#define SMEM_FLOATS (OFF_WV + NC * ID)          // 25600
#define SMEM_BYTES  (SMEM_FLOATS * 4)           // 102400 (100 KB)

// ---- device scratch ----
__device__ float g_P [B_ * NC * IC];            // routing logits (4 MB)
__device__ float g_WV[B_ * NC * ID];            // wv = W @ v     (1 MB)
__device__ float g_Yp[IT * B_ * NC * ID];       // partial Y      (4 MB)
__device__ unsigned g_bar   = 0;                // monotonic barrier counter
__device__ unsigned g_epoch = 0;                // launches completed

// Grid barrier: monotonic counter, wrap-safe compare. All blocks resident
// (occupancy-forced), so spin cannot deadlock.
__device__ __forceinline__ void grid_bar(unsigned target) {
    __syncthreads();
    if (threadIdx.x == 0) {
        __threadfence();                         // release our block's stores
        atomicAdd(&g_bar, 1u);
        while ((int)(*(volatile unsigned*)&g_bar - target) < 0) { }
        __threadfence();                         // acquire others' stores
    }
    __syncthreads();
}

// ============================================================
// Persistent mega-kernel: entire 3-iteration routing in 1 launch.
// grid 256, block 256, 100 KB smem, forced 2 CTA/SM.
// ============================================================
__global__ __launch_bounds__(256, 2) void k_mega(
    const float* __restrict__ X,
    const float* __restrict__ W,
    const float* __restrict__ B0,
    float* __restrict__ OUT)
{
    extern __shared__ float sm[];
    float* xs  = sm + OFF_XS;   // [TI][132]  X tile — persistent all phases
    float* cs  = sm + OFF_C;    // [TI][36]   logits/coeffs (aliased: Wsm in svwv)
    float* wvs = sm + OFF_WV;   // [NC][ID]   wv        (aliased: Ysm+vsm in svwv)

    const int blk  = blockIdx.x;
    const int b    = blk >> 2;          // fused mapping: batch
    const int tt   = blk & 3;           // fused mapping: i-tile
    const int i0   = tt * TI;
    const int t    = threadIdx.x;
    const int lane = t & 31;
    const int w    = t >> 5;
    const int n0   = w * 4;

    // svwv mapping: one n per 32-block group, 8 batches per block
    const int sn  = blk & 31;
    const int sb0 = (blk >> 5) * 8;

    const unsigned base = (*(volatile unsigned*)&g_epoch) * 5u * NBLK;

    // ======== stage X tile ONCE (persistent) ========
    {
        const float4* Xb = (const float4*)(X + ((size_t)b * IC + i0) * ID);
        for (int u = t; u < TI * 32; u += 256) {
            const int r = u >> 5, q = u & 31;
            *(float4*)(xs + r * XS_STRIDE + q * 4) = Xb[r * 32 + q];
        }
    }

    // ================= 3 routing iterations =================
    for (int iter = 0; iter < 3; iter++) {
        if (iter == 0) {
            // logits tile straight from b0
            const float* Pb = B0 + (size_t)b * NC * IC + i0;
            for (int u = t; u < NC * TI; u += 256) {
                const int n = u >> 7, i = u & 127;
                cs[i * C_STRIDE + n] = Pb[(size_t)n * IC + i];
            }
            __syncthreads();
        } else {
            // stage wv[b] (fresh from the svwv phase)
            for (int u = t; u < NC * ID; u += 256)
                wvs[u] = g_WV[(size_t)b * NC * ID + u];
            __syncthreads();

            // ---- uv[n][i] = sum_d xs[i][d] * wv[n][d]  (4n x 4i tile) ----
            float acc[4][4];
#pragma unroll
            for (int k = 0; k < 4; k++)
#pragma unroll
                for (int jj = 0; jj < 4; jj++) acc[k][jj] = 0.f;

#pragma unroll 2
            for (int d = 0; d < ID; d += 4) {
                float4 xq[4];
#pragma unroll
                for (int jj = 0; jj < 4; jj++)
                    xq[jj] = *(const float4*)(xs + (lane + 32 * jj) * XS_STRIDE + d);
#pragma unroll
                for (int k = 0; k < 4; k++) {
                    const float4 wq = *(const float4*)(wvs + (n0 + k) * ID + d);
#pragma unroll
                    for (int jj = 0; jj < 4; jj++) {
                        acc[k][jj] = fmaf(wq.x, xq[jj].x, acc[k][jj]);
                        acc[k][jj] = fmaf(wq.y, xq[jj].y, acc[k][jj]);
                        acc[k][jj] = fmaf(wq.z, xq[jj].z, acc[k][jj]);
                        acc[k][jj] = fmaf(wq.w, xq[jj].w, acc[k][jj]);
                    }
                }
            }

            // b_new = b_prev + uv  (iter1: read B0, persist to g_P for iter2;
            //                       iter2: read g_P — same block wrote it)
            const float* Pprev = (iter == 1) ? B0 : g_P;
#pragma unroll
            for (int k = 0; k < 4; k++)
#pragma unroll
                for (int jj = 0; jj < 4; jj++) {
                    const size_t off = ((size_t)b * NC + n0 + k) * IC + i0 + lane + 32 * jj;
                    const float nb = Pprev[off] + acc[k][jj];
                    if (iter == 1) g_P[off] = nb;
                    cs[(lane + 32 * jj) * C_STRIDE + n0 + k] = nb;
                }
            __syncthreads();
        }

        // ---- softmax over n: 2 threads per i-row ----
        {
            const int i = t >> 1;
            const int h = (t & 1) << 4;
            float* row = cs + i * C_STRIDE + h;
            float m = row[0];
#pragma unroll
            for (int n = 1; n < 16; n++) m = fmaxf(m, row[n]);
            m = fmaxf(m, __shfl_xor_sync(0xffffffffu, m, 1));
            float s = 0.f;
#pragma unroll
            for (int n = 0; n < 16; n++) {
                const float e = __expf(row[n] - m);
                row[n] = e;
                s += e;
            }
            s += __shfl_xor_sync(0xffffffffu, s, 1);
            const float r = __fdividef(1.f, s);
#pragma unroll
            for (int n = 0; n < 16; n++) row[n] *= r;
        }
        __syncthreads();

        // ---- partial Y[n][d] = sum_i c[i][n] * xs[i][d]  (4n x 4d tile) ----
        {
            const int d0 = lane * 4;
            float y[4][4];
#pragma unroll
            for (int k = 0; k < 4; k++)
#pragma unroll
                for (int j = 0; j < 4; j++) y[k][j] = 0.f;

#pragma unroll 2
            for (int i = 0; i < TI; i++) {
                const float4 cq = *(const float4*)(cs + i * C_STRIDE + n0);
                const float4 xv = *(const float4*)(xs + i * XS_STRIDE + d0);
                y[0][0] = fmaf(cq.x, xv.x, y[0][0]);
                y[0][1] = fmaf(cq.x, xv.y, y[0][1]);
                y[0][2] = fmaf(cq.x, xv.z, y[0][2]);
                y[0][3] = fmaf(cq.x, xv.w, y[0][3]);
                y[1][0] = fmaf(cq.y, xv.x, y[1][0]);
                y[1][1] = fmaf(cq.y, xv.y, y[1][1]);
                y[1][2] = fmaf(cq.y, xv.z, y[1][2]);
                y[1][3] = fmaf(cq.y, xv.w, y[1][3]);
                y[2][0] = fmaf(cq.z, xv.x, y[2][0]);
                y[2][1] = fmaf(cq.z, xv.y, y[2][1]);
                y[2][2] = fmaf(cq.z, xv.z, y[2][2]);
                y[2][3] = fmaf(cq.z, xv.w, y[2][3]);
                y[3][0] = fmaf(cq.w, xv.x, y[3][0]);
                y[3][1] = fmaf(cq.w, xv.y, y[3][1]);
                y[3][2] = fmaf(cq.w, xv.z, y[3][2]);
                y[3][3] = fmaf(cq.w, xv.w, y[3][3]);
            }

            float* Yp = g_Yp + (((size_t)tt * B_ + b) * NC + n0) * ID + d0;
#pragma unroll
            for (int k = 0; k < 4; k++)
                *(float4*)(Yp + (size_t)k * ID) = make_float4(y[k][0], y[k][1], y[k][2], y[k][3]);
        }

        // Yp visible to svwv blocks
        grid_bar(base + (unsigned)(2 * iter + 1) * NBLK);

        // ======== svwv phase: block -> (n=sn, batches sb0..sb0+7) ========
        {
            float* Wsm = cs;             // [128][33] = 16.9 KB (cs region 18.4 KB)
            float* Ysm = wvs;            // [8][128]
            float* vsm = wvs + 8 * ID;   // [8][32]

            // stage W[sn] transposed-free: Wsm[d*33+c]
            const float* Wn = W + (size_t)sn * ID * DC;
            for (int u = t; u < ID * DC; u += 256) {
                const int d = u >> 5, c = u & 31;
                Wsm[d * 33 + c] = Wn[u];
            }
            // reduce IT partial Y tiles for 8 batches
            for (int u = t; u < 8 * ID; u += 256) {
                const int bb = u >> 7, d = u & 127;
                float acc = 0.f;
#pragma unroll
                for (int p = 0; p < IT; p++)
                    acc += g_Yp[(((size_t)p * B_ + sb0 + bb) * NC + sn) * ID + d];
                Ysm[bb * ID + d] = acc;
            }
            __syncthreads();

            // warp = batch, lane = output c: s-dot + squash
            {
                const int bb = w, c = lane;
                float s = 0.f;
#pragma unroll 8
                for (int d = 0; d < ID; d++)
                    s = fmaf(Ysm[bb * ID + d], Wsm[d * 33 + c], s);

                float snorm = s * s;
#pragma unroll
                for (int o = 16; o; o >>= 1) snorm += __shfl_xor_sync(0xffffffffu, snorm, o);
                const float v = s * snorm / ((1.f + snorm) * (sqrtf(snorm) + 1e-8f));

                if (iter == 2) {
                    OUT[(((size_t)(sb0 + bb)) * NC + sn) * DC + c] = v;
                } else {
                    vsm[bb * NC + c] = v;
                }
            }

            if (iter < 2) {
                __syncthreads();
                // wv[d] = sum_c W[sn][d][c] * v[c]
                for (int u = t; u < 8 * ID; u += 256) {
                    const int bb = u >> 7, d = u & 127;
                    float acc = 0.f;
#pragma unroll
                    for (int c = 0; c < DC; c++)
                        acc = fmaf(Wsm[d * 33 + c], vsm[bb * NC + c], acc);
                    g_WV[(((size_t)(sb0 + bb)) * NC + sn) * ID + d] = acc;
                }
                // WV visible to fused blocks of next iteration
                grid_bar(base + (unsigned)(2 * iter + 2) * NBLK);
            }
        }
    }

    // bump epoch once per launch (all blocks passed the last barrier already)
    if (blk == 0 && t == 0) {
        __threadfence();
        atomicAdd(&g_epoch, 1u);
    }
}

// ============================================================
// launch
// ============================================================
extern "C" void kernel_launch(void* const* d_in, const int* in_sizes, int n_in,
                              void* d_out, int out_size) {
    const float *X = nullptr, *W = nullptr, *B0 = nullptr;
    for (int i = 0; i < n_in; i++) {
        if      (in_sizes[i] == B_ * IC * ID) X  = (const float*)d_in[i];
        else if (in_sizes[i] == NC * ID * DC) W  = (const float*)d_in[i];
        else if (in_sizes[i] == B_ * NC * IC) B0 = (const float*)d_in[i];
    }
    float* OUT = (float*)d_out;

    cudaFuncSetAttribute(k_mega,
                         cudaFuncAttributeMaxDynamicSharedMemorySize, SMEM_BYTES);

    k_mega<<<NBLK, 256, SMEM_BYTES>>>(X, W, B0, OUT);
}

// round 11
// speedup vs baseline: 1.8545x; 1.3586x over previous
#include <cuda_runtime.h>
#include <cuda_bf16.h>
#include <cstdint>

#define B_  64
#define IC  512
#define ID  128
#define NC  32
#define DC  32
#define IT  4
#define TI  128
#define NBLK 256

#define CST 36      // fp32 cs row stride (floats)
#define BFS 136     // bf16 row stride (elements); 272 B -> 4-bank rotation per row

// byte offsets in dynamic smem
#define CS_OFF   0                       // fp32 cs [128][36] = 18432 (alias: svwv Wsm [128][33])
#define XSB_OFF  18432                   // bf16 xs  [128][136] = 34816
#define XTB_OFF  53248                   // bf16 xsT [128][136] = 34816
#define WVB_OFF  88064                   // bf16 wv  [32][136]  = 8704 (alias: svwv Ysm+vsm)
#define CTB_OFF  96768                   // bf16 cT  [32][136]  = 8704
#define SMEM_BYTES 105472                // 103 KB -> 2 CTA/SM

// ---- device scratch ----
__device__ float g_P [B_ * NC * IC];
__device__ float g_WV[B_ * NC * ID];
__device__ float g_Yp[IT * B_ * NC * ID];
__device__ unsigned g_bar   = 0;
__device__ unsigned g_epoch = 0;

// ---- helpers ----
__device__ __forceinline__ uint32_t smem_u32(const void* p) {
    uint32_t a;
    asm("{ .reg .u64 t; cvta.to.shared.u64 t, %1; cvt.u32.u64 %0, t; }" : "=r"(a) : "l"(p));
    return a;
}
__device__ __forceinline__ uint32_t cvt2(float lo, float hi) {   // -> bf16x2 {lo,hi}
    uint32_t r;
    asm("cvt.rn.bf16x2.f32 %0, %1, %2;" : "=r"(r) : "f"(hi), "f"(lo));
    return r;
}
__device__ __forceinline__ void ldsm_x4(uint32_t& r0, uint32_t& r1, uint32_t& r2,
                                        uint32_t& r3, uint32_t addr) {
    asm volatile("ldmatrix.sync.aligned.m8n8.x4.shared.b16 {%0,%1,%2,%3}, [%4];"
                 : "=r"(r0), "=r"(r1), "=r"(r2), "=r"(r3) : "r"(addr));
}
__device__ __forceinline__ void mma_bf16(float* d, uint32_t a0, uint32_t a1,
                                         uint32_t a2, uint32_t a3,
                                         uint32_t b0, uint32_t b1) {
    asm volatile(
        "mma.sync.aligned.m16n8k16.row.col.f32.bf16.bf16.f32 "
        "{%0,%1,%2,%3}, {%4,%5,%6,%7}, {%8,%9}, {%0,%1,%2,%3};"
        : "+f"(d[0]), "+f"(d[1]), "+f"(d[2]), "+f"(d[3])
        : "r"(a0), "r"(a1), "r"(a2), "r"(a3), "r"(b0), "r"(b1));
}
__device__ __forceinline__ void grid_bar(unsigned target) {
    __syncthreads();
    if (threadIdx.x == 0) {
        __threadfence();
        atomicAdd(&g_bar, 1u);
        while ((int)(*(volatile unsigned*)&g_bar - target) < 0) { }
        __threadfence();
    }
    __syncthreads();
}

// ============================================================
// Persistent mega-kernel, routing GEMMs on bf16 mma.sync.
// grid 256, block 256, 103 KB smem, forced 2 CTA/SM.
// ============================================================
__global__ __launch_bounds__(256, 2) void k_mega(
    const float* __restrict__ X,
    const float* __restrict__ W,
    const float* __restrict__ B0,
    float* __restrict__ OUT)
{
    extern __shared__ __align__(16) char smc[];
    float* cs = (float*)(smc + CS_OFF);
    const uint32_t smb = smem_u32(smc);

    const int blk  = blockIdx.x;
    const int b    = blk >> 2;
    const int tt   = blk & 3;
    const int i0   = tt * TI;
    const int t    = threadIdx.x;
    const int lane = t & 31;
    const int w    = t >> 5;
    const int m0   = w * 16;            // warp's MMA m-tile
    const int sn   = blk & 31;          // svwv: capsule
    const int sb0  = (blk >> 5) * 8;    // svwv: batch group

    const unsigned base = (*(volatile unsigned*)&g_epoch) * 5u * NBLK;

    // fragment address lane maps (shared by A and B ldmatrix.x4)
    const int a_row = m0 + (lane & 15);
    const int a_col = (lane >> 4) << 3;
    const int b_row = (lane & 7) + ((lane >> 4) << 3);
    const int b_col = ((lane >> 3) & 1) << 3;

    const uint32_t a1_base = smb + XSB_OFF + (uint32_t)(a_row * BFS + a_col) * 2;
    const uint32_t a3_base = smb + XTB_OFF + (uint32_t)(a_row * BFS + a_col) * 2;
    const uint32_t b1_base = smb + WVB_OFF + (uint32_t)(b_row * BFS + b_col) * 2;
    const uint32_t b3_base = smb + CTB_OFF + (uint32_t)(b_row * BFS + b_col) * 2;

    // ---- stage bf16 X tile from gmem (once) ----
    {
        const float4* Xb = (const float4*)(X + ((size_t)b * IC + i0) * ID);
        uint32_t* dst = (uint32_t*)(smc + XSB_OFF);
        for (int u = t; u < TI * 32; u += 256) {
            const int r = u >> 5, q = u & 31;
            const float4 v = Xb[r * 32 + q];
            dst[r * (BFS / 2) + 2 * q]     = cvt2(v.x, v.y);
            dst[r * (BFS / 2) + 2 * q + 1] = cvt2(v.z, v.w);
        }
    }
    __syncthreads();
    // ---- in-smem bf16 transpose xs -> xsT (once) ----
    {
        const __nv_bfloat16* s = (const __nv_bfloat16*)(smc + XSB_OFF);
        __nv_bfloat16* d = (__nv_bfloat16*)(smc + XTB_OFF);
        for (int u = t; u < TI * ID; u += 256)
            d[(u >> 7) * BFS + (u & 127)] = s[(u & 127) * BFS + (u >> 7)];
    }
    __syncthreads();

    // ================= 3 routing iterations =================
    for (int iter = 0; iter < 3; iter++) {
        if (iter == 0) {
            const float* Pb = B0 + (size_t)b * NC * IC + i0;
            for (int u = t; u < NC * TI; u += 256) {
                const int n = u >> 7, i = u & 127;
                cs[i * CST + n] = Pb[(size_t)n * IC + i];
            }
            __syncthreads();
        } else {
            // ---- stage wv as bf16 [n][d] (row-major == col-major KxN) ----
            {
                const float* WVb = g_WV + (size_t)b * NC * ID;
                uint32_t* wd = (uint32_t*)(smc + WVB_OFF);
                for (int u = t; u < NC * 64; u += 256) {
                    const int n = u >> 6, p = u & 63;
                    const float2 v = *(const float2*)(WVb + n * ID + 2 * p);
                    wd[n * (BFS / 2) + p] = cvt2(v.x, v.y);
                }
            }
            __syncthreads();

            // ---- phase 1 MMA: uv[i][n] = sum_d x[i][d] * wv[n][d] ----
            float acc[4][4];
#pragma unroll
            for (int k = 0; k < 4; k++)
#pragma unroll
                for (int j = 0; j < 4; j++) acc[k][j] = 0.f;

#pragma unroll
            for (int kk = 0; kk < 8; kk++) {
                uint32_t a0, a1, a2, a3;
                ldsm_x4(a0, a1, a2, a3, a1_base + kk * 32);
#pragma unroll
                for (int np = 0; np < 2; np++) {
                    uint32_t b0, b1, b2, b3;
                    ldsm_x4(b0, b1, b2, b3, b1_base + np * (16 * BFS * 2) + kk * 32);
                    mma_bf16(acc[2 * np],     a0, a1, a2, a3, b0, b1);
                    mma_bf16(acc[2 * np + 1], a0, a1, a2, a3, b2, b3);
                }
            }

            // epilogue: b_new = b_prev + uv
            const float* Pprev = (iter == 1) ? B0 : g_P;
            const int r0 = lane >> 2, c0 = 2 * (lane & 3);
#pragma unroll
            for (int nt = 0; nt < 4; nt++)
#pragma unroll
                for (int rr = 0; rr < 2; rr++) {
                    const int i_loc = m0 + r0 + rr * 8;
#pragma unroll
                    for (int cc = 0; cc < 2; cc++) {
                        const int n = nt * 8 + c0 + cc;
                        const size_t off = ((size_t)b * NC + n) * IC + i0 + i_loc;
                        const float nb = Pprev[off] + acc[nt][rr * 2 + cc];
                        if (iter == 1) g_P[off] = nb;
                        cs[i_loc * CST + n] = nb;
                    }
                }
            __syncthreads();
        }

        // ---- softmax over n (2 threads per i-row) + bf16 cT write ----
        {
            const int i = t >> 1;
            const int h = (t & 1) << 4;
            float* row = cs + i * CST + h;
            float m = row[0];
#pragma unroll
            for (int n = 1; n < 16; n++) m = fmaxf(m, row[n]);
            m = fmaxf(m, __shfl_xor_sync(0xffffffffu, m, 1));
            float s = 0.f;
#pragma unroll
            for (int n = 0; n < 16; n++) {
                const float e = __expf(row[n] - m);
                row[n] = e;
                s += e;
            }
            s += __shfl_xor_sync(0xffffffffu, s, 1);
            const float r = __fdividef(1.f, s);
#pragma unroll
            for (int n = 0; n < 16; n++) row[n] *= r;
            if (iter < 2) {
                __nv_bfloat16* ctb = (__nv_bfloat16*)(smc + CTB_OFF);
#pragma unroll
                for (int n = 0; n < 16; n++)
                    ctb[(h + n) * BFS + i] = __float2bfloat16(row[n]);
            }
        }
        __syncthreads();

        if (iter < 2) {
            // ---- phase 3 MMA: Yp[d][n] = sum_i xT[d][i] * c[i][n] ----
            float acc[4][4];
#pragma unroll
            for (int k = 0; k < 4; k++)
#pragma unroll
                for (int j = 0; j < 4; j++) acc[k][j] = 0.f;

#pragma unroll
            for (int kk = 0; kk < 8; kk++) {
                uint32_t a0, a1, a2, a3;
                ldsm_x4(a0, a1, a2, a3, a3_base + kk * 32);
#pragma unroll
                for (int np = 0; np < 2; np++) {
                    uint32_t b0, b1, b2, b3;
                    ldsm_x4(b0, b1, b2, b3, b3_base + np * (16 * BFS * 2) + kk * 32);
                    mma_bf16(acc[2 * np],     a0, a1, a2, a3, b0, b1);
                    mma_bf16(acc[2 * np + 1], a0, a1, a2, a3, b2, b3);
                }
            }
            const int r0 = lane >> 2, c0 = 2 * (lane & 3);
#pragma unroll
            for (int nt = 0; nt < 4; nt++)
#pragma unroll
                for (int rr = 0; rr < 2; rr++) {
                    const int d_loc = m0 + r0 + rr * 8;
#pragma unroll
                    for (int cc = 0; cc < 2; cc++) {
                        const int n = nt * 8 + c0 + cc;
                        g_Yp[(((size_t)tt * B_ + b) * NC + n) * ID + d_loc] =
                            acc[nt][rr * 2 + cc];
                    }
                }
        } else {
            // ---- final phase 3 in fp32 FFMA, X from gmem (L1/L2-resident) ----
            const int n0f = w * 4;
            const float4* Xb4 = (const float4*)(X + ((size_t)b * IC + i0) * ID) + lane;
            float y[4][4];
#pragma unroll
            for (int k = 0; k < 4; k++)
#pragma unroll
                for (int j = 0; j < 4; j++) y[k][j] = 0.f;
#pragma unroll 2
            for (int i = 0; i < TI; i++) {
                const float4 cq = *(const float4*)(cs + i * CST + n0f);
                const float4 xv = Xb4[i * 32];
                y[0][0] = fmaf(cq.x, xv.x, y[0][0]);
                y[0][1] = fmaf(cq.x, xv.y, y[0][1]);
                y[0][2] = fmaf(cq.x, xv.z, y[0][2]);
                y[0][3] = fmaf(cq.x, xv.w, y[0][3]);
                y[1][0] = fmaf(cq.y, xv.x, y[1][0]);
                y[1][1] = fmaf(cq.y, xv.y, y[1][1]);
                y[1][2] = fmaf(cq.y, xv.z, y[1][2]);
                y[1][3] = fmaf(cq.y, xv.w, y[1][3]);
                y[2][0] = fmaf(cq.z, xv.x, y[2][0]);
                y[2][1] = fmaf(cq.z, xv.y, y[2][1]);
                y[2][2] = fmaf(cq.z, xv.z, y[2][2]);
                y[2][3] = fmaf(cq.z, xv.w, y[2][3]);
                y[3][0] = fmaf(cq.w, xv.x, y[3][0]);
                y[3][1] = fmaf(cq.w, xv.y, y[3][1]);
                y[3][2] = fmaf(cq.w, xv.z, y[3][2]);
                y[3][3] = fmaf(cq.w, xv.w, y[3][3]);
            }
            float* Yp = g_Yp + (((size_t)tt * B_ + b) * NC + n0f) * ID + lane * 4;
#pragma unroll
            for (int k = 0; k < 4; k++)
                *(float4*)(Yp + (size_t)k * ID) = make_float4(y[k][0], y[k][1], y[k][2], y[k][3]);
        }

        grid_bar(base + (unsigned)(2 * iter + 1) * NBLK);

        // ======== svwv: block -> (n=sn, batches sb0..sb0+7), fp32 ========
        {
            float* Wsm = cs;                          // [128][33] over cs region
            float* Ysm = (float*)(smc + WVB_OFF);     // [8][128]
            float* vsm = Ysm + 8 * ID;                // [8][32]

            const float* Wn = W + (size_t)sn * ID * DC;
            for (int u = t; u < ID * DC; u += 256) {
                const int d = u >> 5, c = u & 31;
                Wsm[d * 33 + c] = Wn[u];
            }
            for (int u = t; u < 8 * ID; u += 256) {
                const int bb = u >> 7, d = u & 127;
                float acc = 0.f;
#pragma unroll
                for (int p = 0; p < IT; p++)
                    acc += g_Yp[(((size_t)p * B_ + sb0 + bb) * NC + sn) * ID + d];
                Ysm[bb * ID + d] = acc;
            }
            __syncthreads();

            {
                const int bb = w, c = lane;
                float s = 0.f;
#pragma unroll 8
                for (int d = 0; d < ID; d++)
                    s = fmaf(Ysm[bb * ID + d], Wsm[d * 33 + c], s);

                float snorm = s * s;
#pragma unroll
                for (int o = 16; o; o >>= 1) snorm += __shfl_xor_sync(0xffffffffu, snorm, o);
                const float v = s * snorm / ((1.f + snorm) * (sqrtf(snorm) + 1e-8f));

                if (iter == 2) {
                    OUT[(((size_t)(sb0 + bb)) * NC + sn) * DC + c] = v;
                } else {
                    vsm[bb * NC + c] = v;
                }
            }

            if (iter < 2) {
                __syncthreads();
                for (int u = t; u < 8 * ID; u += 256) {
                    const int bb = u >> 7, d = u & 127;
                    float acc = 0.f;
#pragma unroll
                    for (int c = 0; c < DC; c++)
                        acc = fmaf(Wsm[d * 33 + c], vsm[bb * NC + c], acc);
                    g_WV[(((size_t)(sb0 + bb)) * NC + sn) * ID + d] = acc;
                }
                grid_bar(base + (unsigned)(2 * iter + 2) * NBLK);
            }
        }
    }

    if (blk == 0 && t == 0) {
        __threadfence();
        atomicAdd(&g_epoch, 1u);
    }
}

// ============================================================
// launch
// ============================================================
extern "C" void kernel_launch(void* const* d_in, const int* in_sizes, int n_in,
                              void* d_out, int out_size) {
    const float *X = nullptr, *Wp = nullptr, *B0 = nullptr;
    for (int i = 0; i < n_in; i++) {
        if      (in_sizes[i] == B_ * IC * ID) X  = (const float*)d_in[i];
        else if (in_sizes[i] == NC * ID * DC) Wp = (const float*)d_in[i];
        else if (in_sizes[i] == B_ * NC * IC) B0 = (const float*)d_in[i];
    }
    float* OUT = (float*)d_out;

    cudaFuncSetAttribute(k_mega,
                         cudaFuncAttributeMaxDynamicSharedMemorySize, SMEM_BYTES);

    k_mega<<<NBLK, 256, SMEM_BYTES>>>(X, Wp, B0, OUT);
}

// round 13
// speedup vs baseline: 1.9225x; 1.0367x over previous
#include <cuda_runtime.h>
#include <cuda_bf16.h>
#include <cstdint>

#define B_  64
#define IC  512
#define ID  128
#define NC  32
#define DC  32
#define IT  4
#define TI  128
#define NBLK 256

#define CST 36      // fp32 cs row stride (floats)
#define BFS 136     // bf16 row stride (elements)

// byte offsets in dynamic smem
#define CS_OFF   0                       // fp32 cs [128][36] = 18432 (alias: svwv Wsm)
#define XSB_OFF  18432                   // bf16 xs_hi [128][136] = 34816 (iter2: xsT_lo)
#define XTB_OFF  53248                   // bf16 xsT_hi [128][136] = 34816
#define WVB_OFF  88064                   // bf16 wv [32][136] = 8704 (alias: svwv Ysm+vsm)
#define CTH_OFF  96768                   // bf16 cT_hi [32][136] = 8704
#define CTL_OFF  105472                  // bf16 cT_lo [32][136] = 8704
#define SMEM_BYTES 114176                // 111.5 KB -> 2 CTA/SM (223 KB of 228)

// ---- device scratch ----
__device__ float g_WV[B_ * NC * ID];
__device__ float g_Yp[IT * B_ * NC * ID];
__device__ unsigned g_bar   = 0;
__device__ unsigned g_epoch = 0;

// ---- helpers ----
__device__ __forceinline__ uint32_t smem_u32(const void* p) {
    uint32_t a;
    asm("{ .reg .u64 t; cvta.to.shared.u64 t, %1; cvt.u32.u64 %0, t; }" : "=r"(a) : "l"(p));
    return a;
}
__device__ __forceinline__ uint32_t cvt2(float lo, float hi) {
    uint32_t r;
    asm("cvt.rn.bf16x2.f32 %0, %1, %2;" : "=r"(r) : "f"(hi), "f"(lo));
    return r;
}
__device__ __forceinline__ void ldsm_x4(uint32_t& r0, uint32_t& r1, uint32_t& r2,
                                        uint32_t& r3, uint32_t addr) {
    asm volatile("ldmatrix.sync.aligned.m8n8.x4.shared.b16 {%0,%1,%2,%3}, [%4];"
                 : "=r"(r0), "=r"(r1), "=r"(r2), "=r"(r3) : "r"(addr));
}
__device__ __forceinline__ void mma_bf16(float* d, uint32_t a0, uint32_t a1,
                                         uint32_t a2, uint32_t a3,
                                         uint32_t b0, uint32_t b1) {
    asm volatile(
        "mma.sync.aligned.m16n8k16.row.col.f32.bf16.bf16.f32 "
        "{%0,%1,%2,%3}, {%4,%5,%6,%7}, {%8,%9}, {%0,%1,%2,%3};"
        : "+f"(d[0]), "+f"(d[1]), "+f"(d[2]), "+f"(d[3])
        : "r"(a0), "r"(a1), "r"(a2), "r"(a3), "r"(b0), "r"(b1));
}
__device__ __forceinline__ void grid_bar(unsigned target) {
    __syncthreads();
    if (threadIdx.x == 0) {
        __threadfence();
        atomicAdd(&g_bar, 1u);
        while ((int)(*(volatile unsigned*)&g_bar - target) < 0) { }
        __threadfence();
    }
    __syncthreads();
}

// ============================================================
// Persistent mega-kernel. All four routing GEMMs on bf16 mma.sync;
// final Y-GEMM uses 3-term hi/lo split for fp32-like precision.
// grid 256, block 256, 111.5 KB smem, forced 2 CTA/SM.
// ============================================================
__global__ __launch_bounds__(256, 2) void k_mega(
    const float* __restrict__ X,
    const float* __restrict__ W,
    const float* __restrict__ B0,
    float* __restrict__ OUT)
{
    extern __shared__ __align__(16) char smc[];
    float* cs = (float*)(smc + CS_OFF);
    const uint32_t smb = smem_u32(smc);

    const int blk  = blockIdx.x;
    const int b    = blk >> 2;
    const int tt   = blk & 3;
    const int i0   = tt * TI;
    const int t    = threadIdx.x;
    const int lane = t & 31;
    const int w    = t >> 5;
    const int m0   = w * 16;            // warp's MMA m-tile
    const int sn   = blk & 31;          // svwv: capsule
    const int sb0  = (blk >> 5) * 8;    // svwv: batch group

    const unsigned base = (*(volatile unsigned*)&g_epoch) * 5u * NBLK;

    // fragment address lane maps
    const int a_row = m0 + (lane & 15);
    const int a_col = (lane >> 4) << 3;
    const int b_row = (lane & 7) + ((lane >> 4) << 3);
    const int b_col = ((lane >> 3) & 1) << 3;

    const uint32_t aXS_base = smb + XSB_OFF + (uint32_t)(a_row * BFS + a_col) * 2; // xs_hi / xsT_lo
    const uint32_t aXT_base = smb + XTB_OFF + (uint32_t)(a_row * BFS + a_col) * 2; // xsT_hi
    const uint32_t bWV_base = smb + WVB_OFF + (uint32_t)(b_row * BFS + b_col) * 2;
    const uint32_t bCH_base = smb + CTH_OFF + (uint32_t)(b_row * BFS + b_col) * 2;
    const uint32_t bCL_base = smb + CTL_OFF + (uint32_t)(b_row * BFS + b_col) * 2;

    // fragment epilogue coords
    const int r0 = lane >> 2, c0 = 2 * (lane & 3);

    float breg[16];   // logits carried across iterations (fragment order)

    // ---- stage bf16 X tile (once) ----
    {
        const float4* Xb = (const float4*)(X + ((size_t)b * IC + i0) * ID);
        uint32_t* dst = (uint32_t*)(smc + XSB_OFF);
        for (int u = t; u < TI * 32; u += 256) {
            const int r = u >> 5, q = u & 31;
            const float4 v = Xb[r * 32 + q];
            dst[r * (BFS / 2) + 2 * q]     = cvt2(v.x, v.y);
            dst[r * (BFS / 2) + 2 * q + 1] = cvt2(v.z, v.w);
        }
    }
    __syncthreads();
    // ---- in-smem bf16 transpose xs_hi -> xsT_hi (once) ----
    {
        const __nv_bfloat16* s = (const __nv_bfloat16*)(smc + XSB_OFF);
        __nv_bfloat16* d = (__nv_bfloat16*)(smc + XTB_OFF);
        for (int u = t; u < TI * ID; u += 256)
            d[(u >> 7) * BFS + (u & 127)] = s[(u & 127) * BFS + (u >> 7)];
    }
    __syncthreads();

    // ================= 3 routing iterations =================
    for (int iter = 0; iter < 3; iter++) {
        if (iter == 0) {
            const float* Pb = B0 + (size_t)b * NC * IC + i0;
            for (int u = t; u < NC * TI; u += 256) {
                const int n = u >> 7, i = u & 127;
                cs[i * CST + n] = Pb[(size_t)n * IC + i];
            }
            __syncthreads();
        } else {
            // ---- stage wv bf16 [n][d]; iter1 also stages b0 -> cs ----
            {
                const float* WVb = g_WV + (size_t)b * NC * ID;
                uint32_t* wd = (uint32_t*)(smc + WVB_OFF);
                for (int u = t; u < NC * 64; u += 256) {
                    const int n = u >> 6, p = u & 63;
                    const float2 v = *(const float2*)(WVb + n * ID + 2 * p);
                    wd[n * (BFS / 2) + p] = cvt2(v.x, v.y);
                }
                if (iter == 1) {
                    const float* Pb = B0 + (size_t)b * NC * IC + i0;
                    for (int u = t; u < NC * TI; u += 256) {
                        const int n = u >> 7, i = u & 127;
                        cs[i * CST + n] = Pb[(size_t)n * IC + i];
                    }
                }
            }
            __syncthreads();

            // ---- phase 1 MMA: uv[i][n] = sum_d x[i][d] * wv[n][d] ----
            float acc[4][4];
#pragma unroll
            for (int k = 0; k < 4; k++)
#pragma unroll
                for (int j = 0; j < 4; j++) acc[k][j] = 0.f;

#pragma unroll
            for (int kk = 0; kk < 8; kk++) {
                uint32_t a0, a1, a2, a3;
                ldsm_x4(a0, a1, a2, a3, aXS_base + kk * 32);
#pragma unroll
                for (int np = 0; np < 2; np++) {
                    uint32_t b0r, b1r, b2r, b3r;
                    ldsm_x4(b0r, b1r, b2r, b3r, bWV_base + np * (16 * BFS * 2) + kk * 32);
                    mma_bf16(acc[2 * np],     a0, a1, a2, a3, b0r, b1r);
                    mma_bf16(acc[2 * np + 1], a0, a1, a2, a3, b2r, b3r);
                }
            }

            // epilogue: b_new = b_prev + uv (smem/registers only)
#pragma unroll
            for (int nt = 0; nt < 4; nt++)
#pragma unroll
                for (int rr = 0; rr < 2; rr++) {
                    const int i_loc = m0 + r0 + rr * 8;
#pragma unroll
                    for (int cc = 0; cc < 2; cc++) {
                        const int n = nt * 8 + c0 + cc;
                        const int idx = nt * 4 + rr * 2 + cc;
                        const float prev = (iter == 1) ? cs[i_loc * CST + n] : breg[idx];
                        const float nb = prev + acc[nt][rr * 2 + cc];
                        breg[idx] = nb;
                        cs[i_loc * CST + n] = nb;
                    }
                }
            __syncthreads();

            // iter2: stage xsT_lo into the (now free) xs_hi region
            if (iter == 2) {
                const float* Xg = X + ((size_t)b * IC + i0) * ID;
                __nv_bfloat16* xlo = (__nv_bfloat16*)(smc + XSB_OFF);
                const __nv_bfloat16* xhiT = (const __nv_bfloat16*)(smc + XTB_OFF);
                for (int u = t; u < TI * ID; u += 256) {
                    const int i = u >> 7, d = u & 127;
                    const float hi = __bfloat162float(xhiT[d * BFS + i]);
                    xlo[d * BFS + i] = __float2bfloat16(Xg[(size_t)i * ID + d] - hi);
                }
            }
        }

        // ---- softmax over n (2 threads per i-row) + bf16 cT writes ----
        {
            const int i = t >> 1;
            const int h = (t & 1) << 4;
            float* row = cs + i * CST + h;
            float m = row[0];
#pragma unroll
            for (int n = 1; n < 16; n++) m = fmaxf(m, row[n]);
            m = fmaxf(m, __shfl_xor_sync(0xffffffffu, m, 1));
            float s = 0.f;
#pragma unroll
            for (int n = 0; n < 16; n++) {
                const float e = __expf(row[n] - m);
                row[n] = e;
                s += e;
            }
            s += __shfl_xor_sync(0xffffffffu, s, 1);
            const float r = __fdividef(1.f, s);
            __nv_bfloat16* cth = (__nv_bfloat16*)(smc + CTH_OFF);
            __nv_bfloat16* ctl = (__nv_bfloat16*)(smc + CTL_OFF);
#pragma unroll
            for (int n = 0; n < 16; n++) {
                const float c = row[n] * r;
                row[n] = c;
                const __nv_bfloat16 chb = __float2bfloat16(c);
                cth[(h + n) * BFS + i] = chb;
                if (iter == 2)
                    ctl[(h + n) * BFS + i] = __float2bfloat16(c - __bfloat162float(chb));
            }
        }
        __syncthreads();

        // ---- phase 3 MMA: Yp[d][n] = sum_i xT[d][i] * c[i][n] ----
        {
            float acc[4][4];
#pragma unroll
            for (int k = 0; k < 4; k++)
#pragma unroll
                for (int j = 0; j < 4; j++) acc[k][j] = 0.f;

            if (iter < 2) {
#pragma unroll
                for (int kk = 0; kk < 8; kk++) {
                    uint32_t a0, a1, a2, a3;
                    ldsm_x4(a0, a1, a2, a3, aXT_base + kk * 32);
#pragma unroll
                    for (int np = 0; np < 2; np++) {
                        uint32_t b0r, b1r, b2r, b3r;
                        ldsm_x4(b0r, b1r, b2r, b3r, bCH_base + np * (16 * BFS * 2) + kk * 32);
                        mma_bf16(acc[2 * np],     a0, a1, a2, a3, b0r, b1r);
                        mma_bf16(acc[2 * np + 1], a0, a1, a2, a3, b2r, b3r);
                    }
                }
            } else {
                // 3-term split: x_hi*c_hi + x_hi*c_lo + x_lo*c_hi (fp32 accum)
#pragma unroll
                for (int kk = 0; kk < 8; kk++) {
                    uint32_t h0, h1, h2, h3, l0, l1, l2, l3;
                    ldsm_x4(h0, h1, h2, h3, aXT_base + kk * 32);
                    ldsm_x4(l0, l1, l2, l3, aXS_base + kk * 32);   // xsT_lo
#pragma unroll
                    for (int np = 0; np < 2; np++) {
                        uint32_t bh0, bh1, bh2, bh3, bl0, bl1, bl2, bl3;
                        ldsm_x4(bh0, bh1, bh2, bh3, bCH_base + np * (16 * BFS * 2) + kk * 32);
                        ldsm_x4(bl0, bl1, bl2, bl3, bCL_base + np * (16 * BFS * 2) + kk * 32);
                        mma_bf16(acc[2 * np],     h0, h1, h2, h3, bh0, bh1);
                        mma_bf16(acc[2 * np],     h0, h1, h2, h3, bl0, bl1);
                        mma_bf16(acc[2 * np],     l0, l1, l2, l3, bh0, bh1);
                        mma_bf16(acc[2 * np + 1], h0, h1, h2, h3, bh2, bh3);
                        mma_bf16(acc[2 * np + 1], h0, h1, h2, h3, bl2, bl3);
                        mma_bf16(acc[2 * np + 1], l0, l1, l2, l3, bh2, bh3);
                    }
                }
            }

#pragma unroll
            for (int nt = 0; nt < 4; nt++)
#pragma unroll
                for (int rr = 0; rr < 2; rr++) {
                    const int d_loc = m0 + r0 + rr * 8;
#pragma unroll
                    for (int cc = 0; cc < 2; cc++) {
                        const int n = nt * 8 + c0 + cc;
                        g_Yp[(((size_t)tt * B_ + b) * NC + n) * ID + d_loc] =
                            acc[nt][rr * 2 + cc];
                    }
                }
        }

        grid_bar(base + (unsigned)(2 * iter + 1) * NBLK);

        // ======== svwv: block -> (n=sn, batches sb0..sb0+7), fp32 ========
        {
            float* Wsm = cs;                          // [128][33] over cs region
            float* Ysm = (float*)(smc + WVB_OFF);     // [8][128]
            float* vsm = Ysm + 8 * ID;                // [8][32]

            const float* Wn = W + (size_t)sn * ID * DC;
            for (int u = t; u < ID * DC; u += 256) {
                const int d = u >> 5, c = u & 31;
                Wsm[d * 33 + c] = Wn[u];
            }
            for (int u = t; u < 8 * ID; u += 256) {
                const int bb = u >> 7, d = u & 127;
                float acc = 0.f;
#pragma unroll
                for (int p = 0; p < IT; p++)
                    acc += g_Yp[(((size_t)p * B_ + sb0 + bb) * NC + sn) * ID + d];
                Ysm[bb * ID + d] = acc;
            }
            __syncthreads();

            {
                const int bb = w, c = lane;
                float s = 0.f;
#pragma unroll 8
                for (int d = 0; d < ID; d++)
                    s = fmaf(Ysm[bb * ID + d], Wsm[d * 33 + c], s);

                float snorm = s * s;
#pragma unroll
                for (int o = 16; o; o >>= 1) snorm += __shfl_xor_sync(0xffffffffu, snorm, o);
                const float v = s * snorm / ((1.f + snorm) * (sqrtf(snorm) + 1e-8f));

                if (iter == 2) {
                    OUT[(((size_t)(sb0 + bb)) * NC + sn) * DC + c] = v;
                } else {
                    vsm[bb * NC + c] = v;
                }
            }

            if (iter < 2) {
                __syncthreads();
                for (int u = t; u < 8 * ID; u += 256) {
                    const int bb = u >> 7, d = u & 127;
                    float acc = 0.f;
#pragma unroll
                    for (int c = 0; c < DC; c++)
                        acc = fmaf(Wsm[d * 33 + c], vsm[bb * NC + c], acc);
                    g_WV[(((size_t)(sb0 + bb)) * NC + sn) * ID + d] = acc;
                }
                grid_bar(base + (unsigned)(2 * iter + 2) * NBLK);
            }
        }
    }

    if (blk == 0 && t == 0) {
        __threadfence();
        atomicAdd(&g_epoch, 1u);
    }
}

// ============================================================
// launch
// ============================================================
extern "C" void kernel_launch(void* const* d_in, const int* in_sizes, int n_in,
                              void* d_out, int out_size) {
    const float *X = nullptr, *Wp = nullptr, *B0 = nullptr;
    for (int i = 0; i < n_in; i++) {
        if      (in_sizes[i] == B_ * IC * ID) X  = (const float*)d_in[i];
        else if (in_sizes[i] == NC * ID * DC) Wp = (const float*)d_in[i];
        else if (in_sizes[i] == B_ * NC * IC) B0 = (const float*)d_in[i];
    }
    float* OUT = (float*)d_out;

    cudaFuncSetAttribute(k_mega,
                         cudaFuncAttributeMaxDynamicSharedMemorySize, SMEM_BYTES);

    k_mega<<<NBLK, 256, SMEM_BYTES>>>(X, Wp, B0, OUT);
}

// round 14
// speedup vs baseline: 1.9864x; 1.0332x over previous
#include <cuda_runtime.h>
#include <cuda_bf16.h>
#include <cstdint>

#define B_  64
#define IC  512
#define ID  128
#define NC  32
#define DC  32
#define IT  4
#define TI  128
#define NBLK 256

#define CST 36      // fp32 cs row stride (floats)
#define BFS 136     // bf16 row stride (elements)

// byte offsets in dynamic smem
#define CS_OFF   0                       // fp32 cs [128][36] = 18432 (alias: svwv Wsm)
#define XSB_OFF  18432                   // bf16 xs_hi [128][136] = 34816 (iter2: xsT_lo)
#define XTB_OFF  53248                   // bf16 xsT_hi [128][136] = 34816
#define WVB_OFF  88064                   // bf16 wv [32][136] = 8704 (alias: svwv Ysm+vsm)
#define CTH_OFF  96768                   // bf16 cT_hi [32][136] = 8704
#define CTL_OFF  105472                  // bf16 cT_lo [32][136] = 8704
#define SMEM_BYTES 114176                // 111.5 KB -> 2 CTA/SM

// ---- device scratch ----
__device__ float g_WV[B_ * NC * ID];
__device__ float g_Yp[IT * B_ * NC * ID];
__device__ unsigned g_bar   = 0;
__device__ unsigned g_epoch = 0;

// ---- helpers ----
__device__ __forceinline__ uint32_t smem_u32(const void* p) {
    uint32_t a;
    asm("{ .reg .u64 t; cvta.to.shared.u64 t, %1; cvt.u32.u64 %0, t; }" : "=r"(a) : "l"(p));
    return a;
}
__device__ __forceinline__ uint32_t cvt2(float lo, float hi) {
    uint32_t r;
    asm("cvt.rn.bf16x2.f32 %0, %1, %2;" : "=r"(r) : "f"(hi), "f"(lo));
    return r;
}
// Schraudolph fast exp: FMA + F2I, no MUFU. ~1.5% mantissa-dependent error,
// systematic scale cancels in the softmax ratio. Valid for x in ~[-80, 80];
// routing logits are in [0, ~1.2].
__device__ __forceinline__ float fexp(float x) {
    return __int_as_float((int)fmaf(x, 12102203.0f, 1064986816.0f));
}
__device__ __forceinline__ void ldsm_x4(uint32_t& r0, uint32_t& r1, uint32_t& r2,
                                        uint32_t& r3, uint32_t addr) {
    asm volatile("ldmatrix.sync.aligned.m8n8.x4.shared.b16 {%0,%1,%2,%3}, [%4];"
                 : "=r"(r0), "=r"(r1), "=r"(r2), "=r"(r3) : "r"(addr));
}
__device__ __forceinline__ void mma_bf16(float* d, uint32_t a0, uint32_t a1,
                                         uint32_t a2, uint32_t a3,
                                         uint32_t b0, uint32_t b1) {
    asm volatile(
        "mma.sync.aligned.m16n8k16.row.col.f32.bf16.bf16.f32 "
        "{%0,%1,%2,%3}, {%4,%5,%6,%7}, {%8,%9}, {%0,%1,%2,%3};"
        : "+f"(d[0]), "+f"(d[1]), "+f"(d[2]), "+f"(d[3])
        : "r"(a0), "r"(a1), "r"(a2), "r"(a3), "r"(b0), "r"(b1));
}
__device__ __forceinline__ void grid_bar(unsigned target) {
    __syncthreads();
    if (threadIdx.x == 0) {
        __threadfence();
        atomicAdd(&g_bar, 1u);
        while ((int)(*(volatile unsigned*)&g_bar - target) < 0) { }
        __threadfence();
    }
    __syncthreads();
}

// ============================================================
// Persistent mega-kernel. Routing GEMMs on bf16 mma.sync; final
// Y-GEMM via 3-term hi/lo split; routing softmaxes on fast-exp
// (FMA pipe), final softmax exact (MUFU).
// ============================================================
__global__ __launch_bounds__(256, 2) void k_mega(
    const float* __restrict__ X,
    const float* __restrict__ W,
    const float* __restrict__ B0,
    float* __restrict__ OUT)
{
    extern __shared__ __align__(16) char smc[];
    float* cs = (float*)(smc + CS_OFF);
    const uint32_t smb = smem_u32(smc);

    const int blk  = blockIdx.x;
    const int b    = blk >> 2;
    const int tt   = blk & 3;
    const int i0   = tt * TI;
    const int t    = threadIdx.x;
    const int lane = t & 31;
    const int w    = t >> 5;
    const int m0   = w * 16;
    const int sn   = blk & 31;
    const int sb0  = (blk >> 5) * 8;

    const unsigned base = (*(volatile unsigned*)&g_epoch) * 5u * NBLK;

    const int a_row = m0 + (lane & 15);
    const int a_col = (lane >> 4) << 3;
    const int b_row = (lane & 7) + ((lane >> 4) << 3);
    const int b_col = ((lane >> 3) & 1) << 3;

    const uint32_t aXS_base = smb + XSB_OFF + (uint32_t)(a_row * BFS + a_col) * 2;
    const uint32_t aXT_base = smb + XTB_OFF + (uint32_t)(a_row * BFS + a_col) * 2;
    const uint32_t bWV_base = smb + WVB_OFF + (uint32_t)(b_row * BFS + b_col) * 2;
    const uint32_t bCH_base = smb + CTH_OFF + (uint32_t)(b_row * BFS + b_col) * 2;
    const uint32_t bCL_base = smb + CTL_OFF + (uint32_t)(b_row * BFS + b_col) * 2;

    const int r0 = lane >> 2, c0 = 2 * (lane & 3);

    float breg[16];   // logits carried across iterations (fragment order)

    // ---- stage bf16 X tile (once) ----
    {
        const float4* Xb = (const float4*)(X + ((size_t)b * IC + i0) * ID);
        uint32_t* dst = (uint32_t*)(smc + XSB_OFF);
        for (int u = t; u < TI * 32; u += 256) {
            const int r = u >> 5, q = u & 31;
            const float4 v = Xb[r * 32 + q];
            dst[r * (BFS / 2) + 2 * q]     = cvt2(v.x, v.y);
            dst[r * (BFS / 2) + 2 * q + 1] = cvt2(v.z, v.w);
        }
    }
    __syncthreads();
    // ---- in-smem bf16 transpose xs_hi -> xsT_hi (once) ----
    {
        const __nv_bfloat16* s = (const __nv_bfloat16*)(smc + XSB_OFF);
        __nv_bfloat16* d = (__nv_bfloat16*)(smc + XTB_OFF);
        for (int u = t; u < TI * ID; u += 256)
            d[(u >> 7) * BFS + (u & 127)] = s[(u & 127) * BFS + (u >> 7)];
    }
    __syncthreads();

    // ================= 3 routing iterations =================
    for (int iter = 0; iter < 3; iter++) {
        if (iter == 0) {
            const float* Pb = B0 + (size_t)b * NC * IC + i0;
            for (int u = t; u < NC * TI; u += 256) {
                const int n = u >> 7, i = u & 127;
                cs[i * CST + n] = Pb[(size_t)n * IC + i];
            }
            __syncthreads();
        } else {
            // ---- stage wv bf16 [n][d]; iter1 also stages b0 -> cs ----
            {
                const float* WVb = g_WV + (size_t)b * NC * ID;
                uint32_t* wd = (uint32_t*)(smc + WVB_OFF);
                for (int u = t; u < NC * 64; u += 256) {
                    const int n = u >> 6, p = u & 63;
                    const float2 v = *(const float2*)(WVb + n * ID + 2 * p);
                    wd[n * (BFS / 2) + p] = cvt2(v.x, v.y);
                }
                if (iter == 1) {
                    const float* Pb = B0 + (size_t)b * NC * IC + i0;
                    for (int u = t; u < NC * TI; u += 256) {
                        const int n = u >> 7, i = u & 127;
                        cs[i * CST + n] = Pb[(size_t)n * IC + i];
                    }
                }
            }
            __syncthreads();

            // ---- phase 1 MMA: uv[i][n] = sum_d x[i][d] * wv[n][d] ----
            float acc[4][4];
#pragma unroll
            for (int k = 0; k < 4; k++)
#pragma unroll
                for (int j = 0; j < 4; j++) acc[k][j] = 0.f;

#pragma unroll
            for (int kk = 0; kk < 8; kk++) {
                uint32_t a0, a1, a2, a3;
                ldsm_x4(a0, a1, a2, a3, aXS_base + kk * 32);
#pragma unroll
                for (int np = 0; np < 2; np++) {
                    uint32_t b0r, b1r, b2r, b3r;
                    ldsm_x4(b0r, b1r, b2r, b3r, bWV_base + np * (16 * BFS * 2) + kk * 32);
                    mma_bf16(acc[2 * np],     a0, a1, a2, a3, b0r, b1r);
                    mma_bf16(acc[2 * np + 1], a0, a1, a2, a3, b2r, b3r);
                }
            }

            // epilogue: b_new = b_prev + uv (registers/smem only)
#pragma unroll
            for (int nt = 0; nt < 4; nt++)
#pragma unroll
                for (int rr = 0; rr < 2; rr++) {
                    const int i_loc = m0 + r0 + rr * 8;
#pragma unroll
                    for (int cc = 0; cc < 2; cc++) {
                        const int n = nt * 8 + c0 + cc;
                        const int idx = nt * 4 + rr * 2 + cc;
                        const float prev = (iter == 1) ? cs[i_loc * CST + n] : breg[idx];
                        const float nb = prev + acc[nt][rr * 2 + cc];
                        breg[idx] = nb;
                        cs[i_loc * CST + n] = nb;
                    }
                }
            __syncthreads();

            // iter2: stage xsT_lo into the (now free) xs_hi region
            if (iter == 2) {
                const float* Xg = X + ((size_t)b * IC + i0) * ID;
                __nv_bfloat16* xlo = (__nv_bfloat16*)(smc + XSB_OFF);
                const __nv_bfloat16* xhiT = (const __nv_bfloat16*)(smc + XTB_OFF);
                for (int u = t; u < TI * ID; u += 256) {
                    const int i = u >> 7, d = u & 127;
                    const float hi = __bfloat162float(xhiT[d * BFS + i]);
                    xlo[d * BFS + i] = __float2bfloat16(Xg[(size_t)i * ID + d] - hi);
                }
            }
        }

        // ---- softmax over n (2 threads per i-row) + bf16 cT writes ----
        // iters 0-1: Schraudolph fast-exp (FMA pipe), no max subtraction
        //            (logits in [0, ~1.2]); errors (~1.5%) only perturb the
        //            ~2e-5 routing increments -> ~1e-6 on the output.
        // iter 2:    exact path (max-subtracted __expf) — feeds output.
        {
            const int i = t >> 1;
            const int h = (t & 1) << 4;
            float* row = cs + i * CST + h;
            float s = 0.f;
            if (iter < 2) {
#pragma unroll
                for (int n = 0; n < 16; n++) {
                    const float e = fexp(row[n]);
                    row[n] = e;
                    s += e;
                }
            } else {
                float m = row[0];
#pragma unroll
                for (int n = 1; n < 16; n++) m = fmaxf(m, row[n]);
                m = fmaxf(m, __shfl_xor_sync(0xffffffffu, m, 1));
#pragma unroll
                for (int n = 0; n < 16; n++) {
                    const float e = __expf(row[n] - m);
                    row[n] = e;
                    s += e;
                }
            }
            s += __shfl_xor_sync(0xffffffffu, s, 1);
            const float r = __fdividef(1.f, s);
            __nv_bfloat16* cth = (__nv_bfloat16*)(smc + CTH_OFF);
            __nv_bfloat16* ctl = (__nv_bfloat16*)(smc + CTL_OFF);
#pragma unroll
            for (int n = 0; n < 16; n++) {
                const float c = row[n] * r;
                const __nv_bfloat16 chb = __float2bfloat16(c);
                cth[(h + n) * BFS + i] = chb;
                if (iter == 2)
                    ctl[(h + n) * BFS + i] = __float2bfloat16(c - __bfloat162float(chb));
            }
        }
        __syncthreads();

        // ---- phase 3 MMA: Yp[d][n] = sum_i xT[d][i] * c[i][n] ----
        {
            float acc[4][4];
#pragma unroll
            for (int k = 0; k < 4; k++)
#pragma unroll
                for (int j = 0; j < 4; j++) acc[k][j] = 0.f;

            if (iter < 2) {
#pragma unroll
                for (int kk = 0; kk < 8; kk++) {
                    uint32_t a0, a1, a2, a3;
                    ldsm_x4(a0, a1, a2, a3, aXT_base + kk * 32);
#pragma unroll
                    for (int np = 0; np < 2; np++) {
                        uint32_t b0r, b1r, b2r, b3r;
                        ldsm_x4(b0r, b1r, b2r, b3r, bCH_base + np * (16 * BFS * 2) + kk * 32);
                        mma_bf16(acc[2 * np],     a0, a1, a2, a3, b0r, b1r);
                        mma_bf16(acc[2 * np + 1], a0, a1, a2, a3, b2r, b3r);
                    }
                }
            } else {
                // 3-term split: x_hi*c_hi + x_hi*c_lo + x_lo*c_hi (fp32 accum)
#pragma unroll
                for (int kk = 0; kk < 8; kk++) {
                    uint32_t h0, h1, h2, h3, l0, l1, l2, l3;
                    ldsm_x4(h0, h1, h2, h3, aXT_base + kk * 32);
                    ldsm_x4(l0, l1, l2, l3, aXS_base + kk * 32);   // xsT_lo
#pragma unroll
                    for (int np = 0; np < 2; np++) {
                        uint32_t bh0, bh1, bh2, bh3, bl0, bl1, bl2, bl3;
                        ldsm_x4(bh0, bh1, bh2, bh3, bCH_base + np * (16 * BFS * 2) + kk * 32);
                        ldsm_x4(bl0, bl1, bl2, bl3, bCL_base + np * (16 * BFS * 2) + kk * 32);
                        mma_bf16(acc[2 * np],     h0, h1, h2, h3, bh0, bh1);
                        mma_bf16(acc[2 * np],     h0, h1, h2, h3, bl0, bl1);
                        mma_bf16(acc[2 * np],     l0, l1, l2, l3, bh0, bh1);
                        mma_bf16(acc[2 * np + 1], h0, h1, h2, h3, bh2, bh3);
                        mma_bf16(acc[2 * np + 1], h0, h1, h2, h3, bl2, bl3);
                        mma_bf16(acc[2 * np + 1], l0, l1, l2, l3, bh2, bh3);
                    }
                }
            }

#pragma unroll
            for (int nt = 0; nt < 4; nt++)
#pragma unroll
                for (int rr = 0; rr < 2; rr++) {
                    const int d_loc = m0 + r0 + rr * 8;
#pragma unroll
                    for (int cc = 0; cc < 2; cc++) {
                        const int n = nt * 8 + c0 + cc;
                        g_Yp[(((size_t)tt * B_ + b) * NC + n) * ID + d_loc] =
                            acc[nt][rr * 2 + cc];
                    }
                }
        }

        grid_bar(base + (unsigned)(2 * iter + 1) * NBLK);

        // ======== svwv: block -> (n=sn, batches sb0..sb0+7), fp32 ========
        {
            float* Wsm = cs;
            float* Ysm = (float*)(smc + WVB_OFF);
            float* vsm = Ysm + 8 * ID;

            const float* Wn = W + (size_t)sn * ID * DC;
            for (int u = t; u < ID * DC; u += 256) {
                const int d = u >> 5, c = u & 31;
                Wsm[d * 33 + c] = Wn[u];
            }
            for (int u = t; u < 8 * ID; u += 256) {
                const int bb = u >> 7, d = u & 127;
                float acc = 0.f;
#pragma unroll
                for (int p = 0; p < IT; p++)
                    acc += g_Yp[(((size_t)p * B_ + sb0 + bb) * NC + sn) * ID + d];
                Ysm[bb * ID + d] = acc;
            }
            __syncthreads();

            {
                const int bb = w, c = lane;
                float s = 0.f;
#pragma unroll 8
                for (int d = 0; d < ID; d++)
                    s = fmaf(Ysm[bb * ID + d], Wsm[d * 33 + c], s);

                float snorm = s * s;
#pragma unroll
                for (int o = 16; o; o >>= 1) snorm += __shfl_xor_sync(0xffffffffu, snorm, o);
                const float v = s * snorm / ((1.f + snorm) * (sqrtf(snorm) + 1e-8f));

                if (iter == 2) {
                    OUT[(((size_t)(sb0 + bb)) * NC + sn) * DC + c] = v;
                } else {
                    vsm[bb * NC + c] = v;
                }
            }

            if (iter < 2) {
                __syncthreads();
                for (int u = t; u < 8 * ID; u += 256) {
                    const int bb = u >> 7, d = u & 127;
                    float acc = 0.f;
#pragma unroll
                    for (int c = 0; c < DC; c++)
                        acc = fmaf(Wsm[d * 33 + c], vsm[bb * NC + c], acc);
                    g_WV[(((size_t)(sb0 + bb)) * NC + sn) * ID + d] = acc;
                }
                grid_bar(base + (unsigned)(2 * iter + 2) * NBLK);
            }
        }
    }

    if (blk == 0 && t == 0) {
        __threadfence();
        atomicAdd(&g_epoch, 1u);
    }
}

// ============================================================
// launch
// ============================================================
extern "C" void kernel_launch(void* const* d_in, const int* in_sizes, int n_in,
                              void* d_out, int out_size) {
    const float *X = nullptr, *Wp = nullptr, *B0 = nullptr;
    for (int i = 0; i < n_in; i++) {
        if      (in_sizes[i] == B_ * IC * ID) X  = (const float*)d_in[i];
        else if (in_sizes[i] == NC * ID * DC) Wp = (const float*)d_in[i];
        else if (in_sizes[i] == B_ * NC * IC) B0 = (const float*)d_in[i];
    }
    float* OUT = (float*)d_out;

    cudaFuncSetAttribute(k_mega,
                         cudaFuncAttributeMaxDynamicSharedMemorySize, SMEM_BYTES);

    k_mega<<<NBLK, 256, SMEM_BYTES>>>(X, Wp, B0, OUT);
}